// round 1
// baseline (speedup 1.0000x reference)
#include <cuda_runtime.h>
#include <math.h>

#define NLAYERS 12
#define D 256
#define H 8
#define DK 32
#define FFD 1024
#define BATCH 32
#define SEQ 448
#define NTOK (BATCH*SEQ)   /* 14336 */

// ---------------- scratch (no allocations allowed) ----------------
__device__ float g_nx[NTOK * D];
__device__ float g_q [NTOK * D];
__device__ float g_k [NTOK * D];
__device__ float g_v [NTOK * D];
__device__ float g_ao[NTOK * D];
__device__ float g_h [NTOK * FFD];

// ---------------- pos-emb add:  x = x_in + pos[l] ----------------
__global__ void add_pos_kernel(const float* __restrict__ xin,
                               const float* __restrict__ pos,
                               float* __restrict__ xout) {
    int idx = blockIdx.x * blockDim.x + threadIdx.x;   // float4 index
    int row = idx >> 6;            // token (64 float4 per row)
    int c4  = idx & 63;
    int l   = row % SEQ;
    float4 xv = ((const float4*)xin)[idx];
    float4 pv = ((const float4*)pos)[l * 64 + c4];
    xv.x += pv.x; xv.y += pv.y; xv.z += pv.z; xv.w += pv.w;
    ((float4*)xout)[idx] = xv;
}

// ---------------- LayerNorm: one warp per token ----------------
__global__ void ln_kernel(const float* __restrict__ x,
                          const float* __restrict__ gam,
                          const float* __restrict__ bet,
                          float* __restrict__ out) {
    int warp = threadIdx.x >> 5, lane = threadIdx.x & 31;
    int token = blockIdx.x * 8 + warp;
    const float4* xr = (const float4*)(x + (size_t)token * D);
    float4 v0 = xr[lane];
    float4 v1 = xr[lane + 32];
    float s = v0.x + v0.y + v0.z + v0.w + v1.x + v1.y + v1.z + v1.w;
    #pragma unroll
    for (int o = 16; o > 0; o >>= 1) s += __shfl_xor_sync(0xffffffffu, s, o);
    float mu = s * (1.0f / 256.0f);
    float d0x = v0.x - mu, d0y = v0.y - mu, d0z = v0.z - mu, d0w = v0.w - mu;
    float d1x = v1.x - mu, d1y = v1.y - mu, d1z = v1.z - mu, d1w = v1.w - mu;
    float ss = d0x*d0x + d0y*d0y + d0z*d0z + d0w*d0w
             + d1x*d1x + d1y*d1y + d1z*d1z + d1w*d1w;
    #pragma unroll
    for (int o = 16; o > 0; o >>= 1) ss += __shfl_xor_sync(0xffffffffu, ss, o);
    float inv = rsqrtf(ss * (1.0f / 256.0f) + 1e-6f);
    float4 g0 = ((const float4*)gam)[lane];
    float4 g1 = ((const float4*)gam)[lane + 32];
    float4 b0 = ((const float4*)bet)[lane];
    float4 b1 = ((const float4*)bet)[lane + 32];
    float4 o0, o1;
    o0.x = d0x * inv * g0.x + b0.x;  o0.y = d0y * inv * g0.y + b0.y;
    o0.z = d0z * inv * g0.z + b0.z;  o0.w = d0w * inv * g0.w + b0.w;
    o1.x = d1x * inv * g1.x + b1.x;  o1.y = d1y * inv * g1.y + b1.y;
    o1.z = d1z * inv * g1.z + b1.z;  o1.w = d1w * inv * g1.w + b1.w;
    float4* outr = (float4*)(out + (size_t)token * D);
    outr[lane] = o0;
    outr[lane + 32] = o1;
}

// ---------------- GEMM 128x128x8, 8x8 per thread ----------------
// EPI: 0 = store (bias), 1 = gelu(bias+acc), 2 = residual add into C
__device__ __forceinline__ float gelu_exact(float x) {
    return 0.5f * x * (1.0f + erff(x * 0.7071067811865475f));
}

template<int EPI>
__global__ void __launch_bounds__(256, 2)
gemm_k(const float* __restrict__ A,
       const float* __restrict__ W0, const float* __restrict__ W1, const float* __restrict__ W2,
       const float* __restrict__ b0, const float* __restrict__ b1, const float* __restrict__ b2,
       float* __restrict__ C0, float* __restrict__ C1, float* __restrict__ C2,
       int M, int N, int K) {
    int z = blockIdx.z;
    const float* W    = (z == 0) ? W0 : ((z == 1) ? W1 : W2);
    const float* bias = (z == 0) ? b0 : ((z == 1) ? b1 : b2);
    float*       C    = (z == 0) ? C0 : ((z == 1) ? C1 : C2);

    __shared__ float As[8][128];
    __shared__ float Bs[8][128];

    int tid = threadIdx.x;
    int tx = tid & 15;       // 0..15
    int ty = tid >> 4;       // 0..15
    int row0 = blockIdx.y * 128;
    int col0 = blockIdx.x * 128;

    float acc[8][8];
    #pragma unroll
    for (int i = 0; i < 8; i++)
        #pragma unroll
        for (int j = 0; j < 8; j++) acc[i][j] = 0.0f;

    int arow  = tid >> 1;            // 0..127
    int apart = (tid & 1) * 4;       // 0 or 4
    int brow  = tid >> 5;            // 0..7
    int bcol  = (tid & 31) * 4;      // 0..124

    const float* Aptr = A + (size_t)(row0 + arow) * K + apart;
    const float* Wptr = W + (size_t)brow * N + col0 + bcol;

    for (int kt = 0; kt < K; kt += 8) {
        float4 av  = *(const float4*)(Aptr + kt);
        float4 bvv = *(const float4*)(Wptr + (size_t)kt * N);
        As[apart + 0][arow] = av.x;
        As[apart + 1][arow] = av.y;
        As[apart + 2][arow] = av.z;
        As[apart + 3][arow] = av.w;
        *(float4*)(&Bs[brow][bcol]) = bvv;
        __syncthreads();
        #pragma unroll
        for (int kk = 0; kk < 8; kk++) {
            float a[8], bb[8];
            *(float4*)(a)      = *(const float4*)(&As[kk][ty * 4]);
            *(float4*)(a + 4)  = *(const float4*)(&As[kk][64 + ty * 4]);
            *(float4*)(bb)     = *(const float4*)(&Bs[kk][tx * 4]);
            *(float4*)(bb + 4) = *(const float4*)(&Bs[kk][64 + tx * 4]);
            #pragma unroll
            for (int i = 0; i < 8; i++)
                #pragma unroll
                for (int j = 0; j < 8; j++)
                    acc[i][j] = fmaf(a[i], bb[j], acc[i][j]);
        }
        __syncthreads();
    }

    #pragma unroll
    for (int i = 0; i < 8; i++) {
        int r = row0 + ((i < 4) ? (ty * 4 + i) : (64 + ty * 4 + i - 4));
        float* crow = C + (size_t)r * N;
        #pragma unroll
        for (int jb = 0; jb < 2; jb++) {
            int c = col0 + jb * 64 + tx * 4;
            float4 bs4 = *(const float4*)(bias + c);
            float4 res;
            res.x = acc[i][jb * 4 + 0] + bs4.x;
            res.y = acc[i][jb * 4 + 1] + bs4.y;
            res.z = acc[i][jb * 4 + 2] + bs4.z;
            res.w = acc[i][jb * 4 + 3] + bs4.w;
            if (EPI == 1) {
                res.x = gelu_exact(res.x); res.y = gelu_exact(res.y);
                res.z = gelu_exact(res.z); res.w = gelu_exact(res.w);
            }
            if (EPI == 2) {
                float4 old = *(const float4*)(crow + c);
                res.x += old.x; res.y += old.y; res.z += old.z; res.w += old.w;
            }
            *(float4*)(crow + c) = res;
        }
    }
}

// ---------------- fused attention: one block per (b,h) ----------------
#define KPAD 36
__global__ void attn_kernel(const float* __restrict__ q,
                            const float* __restrict__ k,
                            const float* __restrict__ v,
                            const unsigned char* __restrict__ mask,
                            float* __restrict__ o) {
    extern __shared__ float sm[];
    float* Ks = sm;                    // [SEQ][KPAD]
    float* Vs = sm + SEQ * KPAD;       // [SEQ][KPAD]
    int bh = blockIdx.x;
    int b = bh >> 3, h = bh & 7;
    int tid = threadIdx.x;
    size_t base = (size_t)b * SEQ * D + (size_t)h * DK;

    for (int idx = tid; idx < SEQ * DK; idx += 256) {
        int j = idx >> 5, d = idx & 31;
        size_t gi = base + (size_t)j * D + d;
        Ks[j * KPAD + d] = k[gi];
        Vs[j * KPAD + d] = v[gi];
    }
    __syncthreads();

    int warp = tid >> 5, lane = tid & 31;
    const float scale = 0.17677669529663687f;   // 1/sqrt(32)

    for (int i = warp; i < SEQ; i += 8) {
        // query row into registers (broadcast across lanes)
        float qr[32];
        const float4* qp = (const float4*)(q + base + (size_t)i * D);
        #pragma unroll
        for (int t4 = 0; t4 < 8; t4++) {
            float4 tq = qp[t4];
            qr[t4 * 4 + 0] = tq.x; qr[t4 * 4 + 1] = tq.y;
            qr[t4 * 4 + 2] = tq.z; qr[t4 * 4 + 3] = tq.w;
        }
        // scores: lane handles keys j = t*32 + lane
        float p[14];
        float mx = -1e30f;
        #pragma unroll
        for (int t = 0; t < 14; t++) {
            int j = t * 32 + lane;
            const float* kp = Ks + j * KPAD;
            float s = 0.0f;
            #pragma unroll
            for (int d4 = 0; d4 < 8; d4++) {
                float4 kk = *(const float4*)(kp + d4 * 4);
                s = fmaf(qr[d4 * 4 + 0], kk.x, s);
                s = fmaf(qr[d4 * 4 + 1], kk.y, s);
                s = fmaf(qr[d4 * 4 + 2], kk.z, s);
                s = fmaf(qr[d4 * 4 + 3], kk.w, s);
            }
            s *= scale;
            if (mask[b * SEQ + j]) s = -10000.0f;
            p[t] = s;
            mx = fmaxf(mx, s);
        }
        #pragma unroll
        for (int off = 16; off > 0; off >>= 1)
            mx = fmaxf(mx, __shfl_xor_sync(0xffffffffu, mx, off));
        float sum = 0.0f;
        #pragma unroll
        for (int t = 0; t < 14; t++) { p[t] = __expf(p[t] - mx); sum += p[t]; }
        #pragma unroll
        for (int off = 16; off > 0; off >>= 1)
            sum += __shfl_xor_sync(0xffffffffu, sum, off);
        float inv = 1.0f / sum;
        // P @ V : lane owns output dim d = lane
        float acc = 0.0f;
        #pragma unroll
        for (int t = 0; t < 14; t++) {
            #pragma unroll
            for (int jj = 0; jj < 32; jj++) {
                float pj = __shfl_sync(0xffffffffu, p[t], jj);
                acc = fmaf(pj, Vs[(t * 32 + jj) * KPAD + lane], acc);
            }
        }
        o[base + (size_t)i * D + lane] = acc * inv;
    }
}

// ---------------- launch ----------------
extern "C" void kernel_launch(void* const* d_in, const int* in_sizes, int n_in,
                              void* d_out, int out_size) {
    const float* x_in = (const float*)d_in[0];
    const unsigned char* mask = (const unsigned char*)d_in[1];
    const float* pos  = (const float*)d_in[2];
    const float* Wq   = (const float*)d_in[3];
    const float* bq   = (const float*)d_in[4];
    const float* Wk   = (const float*)d_in[5];
    const float* bk   = (const float*)d_in[6];
    const float* Wv   = (const float*)d_in[7];
    const float* bv   = (const float*)d_in[8];
    const float* Wo   = (const float*)d_in[9];
    const float* bo   = (const float*)d_in[10];
    const float* W1   = (const float*)d_in[11];
    const float* bf1  = (const float*)d_in[12];
    const float* W2   = (const float*)d_in[13];
    const float* bf2  = (const float*)d_in[14];
    const float* ln1g = (const float*)d_in[15];
    const float* ln1b = (const float*)d_in[16];
    const float* ln2g = (const float*)d_in[17];
    const float* ln2b = (const float*)d_in[18];
    float* x = (float*)d_out;            // residual stream lives in d_out

    float *nx, *q, *k, *v, *ao, *hb;
    cudaGetSymbolAddress((void**)&nx, g_nx);
    cudaGetSymbolAddress((void**)&q,  g_q);
    cudaGetSymbolAddress((void**)&k,  g_k);
    cudaGetSymbolAddress((void**)&v,  g_v);
    cudaGetSymbolAddress((void**)&ao, g_ao);
    cudaGetSymbolAddress((void**)&hb, g_h);

    int smem_attn = 2 * SEQ * KPAD * sizeof(float);   // 129024 B
    cudaFuncSetAttribute(attn_kernel,
                         cudaFuncAttributeMaxDynamicSharedMemorySize, smem_attn);

    add_pos_kernel<<<(NTOK * D / 4) / 256, 256>>>(x_in, pos, x);

    for (int l = 0; l < NLAYERS; l++) {
        const float* wq = Wq + (size_t)l * D * D;
        const float* wk = Wk + (size_t)l * D * D;
        const float* wv = Wv + (size_t)l * D * D;
        const float* wo = Wo + (size_t)l * D * D;
        const float* w1 = W1 + (size_t)l * D * FFD;
        const float* w2 = W2 + (size_t)l * FFD * D;

        ln_kernel<<<NTOK / 8, 256>>>(x, ln1g + l * D, ln1b + l * D, nx);

        gemm_k<0><<<dim3(2, 112, 3), 256>>>(nx, wq, wk, wv,
                                            bq + l * D, bk + l * D, bv + l * D,
                                            q, k, v, NTOK, D, D);

        attn_kernel<<<BATCH * H, 256, smem_attn>>>(q, k, v, mask, ao);

        gemm_k<2><<<dim3(2, 112, 1), 256>>>(ao, wo, wo, wo,
                                            bo + l * D, bo + l * D, bo + l * D,
                                            x, x, x, NTOK, D, D);

        ln_kernel<<<NTOK / 8, 256>>>(x, ln2g + l * D, ln2b + l * D, nx);

        gemm_k<1><<<dim3(8, 112, 1), 256>>>(nx, w1, w1, w1,
                                            bf1 + l * FFD, bf1 + l * FFD, bf1 + l * FFD,
                                            hb, hb, hb, NTOK, FFD, D);

        gemm_k<2><<<dim3(2, 112, 1), 256>>>(hb, w2, w2, w2,
                                            bf2 + l * D, bf2 + l * D, bf2 + l * D,
                                            x, x, x, NTOK, D, FFD);
    }
}

// round 2
// speedup vs baseline: 1.6063x; 1.6063x over previous
#include <cuda_runtime.h>
#include <math.h>

#define NLAYERS 12
#define D 256
#define H 8
#define DK 32
#define FFD 1024
#define BATCH 32
#define SEQ 448
#define NTOK (BATCH*SEQ)   /* 14336 */

// ---------------- scratch (no allocations allowed) ----------------
__device__ float g_nx[NTOK * D];
__device__ float g_q [NTOK * D];
__device__ float g_k [NTOK * D];
__device__ float g_v [NTOK * D];
__device__ float g_ao[NTOK * D];
__device__ float g_h [NTOK * FFD];

// ---------------- pos-emb add:  x = x_in + pos[l] ----------------
__global__ void add_pos_kernel(const float* __restrict__ xin,
                               const float* __restrict__ pos,
                               float* __restrict__ xout) {
    int idx = blockIdx.x * blockDim.x + threadIdx.x;   // float4 index
    int row = idx >> 6;            // token (64 float4 per row)
    int c4  = idx & 63;
    int l   = row % SEQ;
    float4 xv = ((const float4*)xin)[idx];
    float4 pv = ((const float4*)pos)[l * 64 + c4];
    xv.x += pv.x; xv.y += pv.y; xv.z += pv.z; xv.w += pv.w;
    ((float4*)xout)[idx] = xv;
}

// ---------------- LayerNorm: one warp per token ----------------
__global__ void ln_kernel(const float* __restrict__ x,
                          const float* __restrict__ gam,
                          const float* __restrict__ bet,
                          float* __restrict__ out) {
    int warp = threadIdx.x >> 5, lane = threadIdx.x & 31;
    int token = blockIdx.x * 8 + warp;
    const float4* xr = (const float4*)(x + (size_t)token * D);
    float4 v0 = xr[lane];
    float4 v1 = xr[lane + 32];
    float s = v0.x + v0.y + v0.z + v0.w + v1.x + v1.y + v1.z + v1.w;
    #pragma unroll
    for (int o = 16; o > 0; o >>= 1) s += __shfl_xor_sync(0xffffffffu, s, o);
    float mu = s * (1.0f / 256.0f);
    float d0x = v0.x - mu, d0y = v0.y - mu, d0z = v0.z - mu, d0w = v0.w - mu;
    float d1x = v1.x - mu, d1y = v1.y - mu, d1z = v1.z - mu, d1w = v1.w - mu;
    float ss = d0x*d0x + d0y*d0y + d0z*d0z + d0w*d0w
             + d1x*d1x + d1y*d1y + d1z*d1z + d1w*d1w;
    #pragma unroll
    for (int o = 16; o > 0; o >>= 1) ss += __shfl_xor_sync(0xffffffffu, ss, o);
    float inv = rsqrtf(ss * (1.0f / 256.0f) + 1e-6f);
    float4 g0 = ((const float4*)gam)[lane];
    float4 g1 = ((const float4*)gam)[lane + 32];
    float4 b0 = ((const float4*)bet)[lane];
    float4 b1 = ((const float4*)bet)[lane + 32];
    float4 o0, o1;
    o0.x = d0x * inv * g0.x + b0.x;  o0.y = d0y * inv * g0.y + b0.y;
    o0.z = d0z * inv * g0.z + b0.z;  o0.w = d0w * inv * g0.w + b0.w;
    o1.x = d1x * inv * g1.x + b1.x;  o1.y = d1y * inv * g1.y + b1.y;
    o1.z = d1z * inv * g1.z + b1.z;  o1.w = d1w * inv * g1.w + b1.w;
    float4* outr = (float4*)(out + (size_t)token * D);
    outr[lane] = o0;
    outr[lane + 32] = o1;
}

// ---------------- GEMM 128x128x8, 8x8 per thread ----------------
// EPI: 0 = store (bias), 1 = gelu(bias+acc), 2 = residual add into C
__device__ __forceinline__ float gelu_exact(float x) {
    return 0.5f * x * (1.0f + erff(x * 0.7071067811865475f));
}

template<int EPI>
__global__ void __launch_bounds__(256, 2)
gemm_k(const float* __restrict__ A,
       const float* __restrict__ W0, const float* __restrict__ W1, const float* __restrict__ W2,
       const float* __restrict__ b0, const float* __restrict__ b1, const float* __restrict__ b2,
       float* __restrict__ C0, float* __restrict__ C1, float* __restrict__ C2,
       int M, int N, int K) {
    int z = blockIdx.z;
    const float* W    = (z == 0) ? W0 : ((z == 1) ? W1 : W2);
    const float* bias = (z == 0) ? b0 : ((z == 1) ? b1 : b2);
    float*       C    = (z == 0) ? C0 : ((z == 1) ? C1 : C2);

    __shared__ float As[8][128];
    __shared__ float Bs[8][128];

    int tid = threadIdx.x;
    int tx = tid & 15;       // 0..15
    int ty = tid >> 4;       // 0..15
    int row0 = blockIdx.y * 128;
    int col0 = blockIdx.x * 128;

    float acc[8][8];
    #pragma unroll
    for (int i = 0; i < 8; i++)
        #pragma unroll
        for (int j = 0; j < 8; j++) acc[i][j] = 0.0f;

    int arow  = tid >> 1;            // 0..127
    int apart = (tid & 1) * 4;       // 0 or 4
    int brow  = tid >> 5;            // 0..7
    int bcol  = (tid & 31) * 4;      // 0..124

    const float* Aptr = A + (size_t)(row0 + arow) * K + apart;
    const float* Wptr = W + (size_t)brow * N + col0 + bcol;

    for (int kt = 0; kt < K; kt += 8) {
        float4 av  = *(const float4*)(Aptr + kt);
        float4 bvv = *(const float4*)(Wptr + (size_t)kt * N);
        As[apart + 0][arow] = av.x;
        As[apart + 1][arow] = av.y;
        As[apart + 2][arow] = av.z;
        As[apart + 3][arow] = av.w;
        *(float4*)(&Bs[brow][bcol]) = bvv;
        __syncthreads();
        #pragma unroll
        for (int kk = 0; kk < 8; kk++) {
            float a[8], bb[8];
            *(float4*)(a)      = *(const float4*)(&As[kk][ty * 4]);
            *(float4*)(a + 4)  = *(const float4*)(&As[kk][64 + ty * 4]);
            *(float4*)(bb)     = *(const float4*)(&Bs[kk][tx * 4]);
            *(float4*)(bb + 4) = *(const float4*)(&Bs[kk][64 + tx * 4]);
            #pragma unroll
            for (int i = 0; i < 8; i++)
                #pragma unroll
                for (int j = 0; j < 8; j++)
                    acc[i][j] = fmaf(a[i], bb[j], acc[i][j]);
        }
        __syncthreads();
    }

    #pragma unroll
    for (int i = 0; i < 8; i++) {
        int r = row0 + ((i < 4) ? (ty * 4 + i) : (64 + ty * 4 + i - 4));
        float* crow = C + (size_t)r * N;
        #pragma unroll
        for (int jb = 0; jb < 2; jb++) {
            int c = col0 + jb * 64 + tx * 4;
            float4 bs4 = *(const float4*)(bias + c);
            float4 res;
            res.x = acc[i][jb * 4 + 0] + bs4.x;
            res.y = acc[i][jb * 4 + 1] + bs4.y;
            res.z = acc[i][jb * 4 + 2] + bs4.z;
            res.w = acc[i][jb * 4 + 3] + bs4.w;
            if (EPI == 1) {
                res.x = gelu_exact(res.x); res.y = gelu_exact(res.y);
                res.z = gelu_exact(res.z); res.w = gelu_exact(res.w);
            }
            if (EPI == 2) {
                float4 old = *(const float4*)(crow + c);
                res.x += old.x; res.y += old.y; res.z += old.z; res.w += old.w;
            }
            *(float4*)(crow + c) = res;
        }
    }
}

// ---------------- fused attention v2: one block per (b,h) ----------------
// 8 warps x 256 threads. Each warp processes 2 query rows at a time
// (28 pairs per warp). Per key row: 8 LDS.128 feed 64 FMAs (2 rows).
// P@V: per-lane partial output vectors + transposed butterfly reduction
// (31 shfl per row instead of 448).
#define KPAD 36            /* floats per row: 9 float4 -> conflict-free */

__global__ void __launch_bounds__(256)
attn_kernel(const float* __restrict__ q,
            const float* __restrict__ k,
            const float* __restrict__ v,
            const unsigned char* __restrict__ mask,
            float* __restrict__ o) {
    extern __shared__ float sm[];
    float4* Ks4 = (float4*)sm;                       // [SEQ][9]
    float4* Vs4 = (float4*)(sm + SEQ * KPAD);        // [SEQ][9]
    int bh = blockIdx.x;
    int b = bh >> 3, h = bh & 7;
    int tid = threadIdx.x;
    int warp = tid >> 5, lane = tid & 31;
    size_t base = (size_t)b * SEQ * D + (size_t)h * DK;

    // cooperative K/V load (vectorized, coalesced)
    for (int idx = tid; idx < SEQ * 8; idx += 256) {
        int j = idx >> 3, d4 = idx & 7;
        size_t gi = base + (size_t)j * D + d4 * 4;
        Ks4[j * 9 + d4] = *(const float4*)(k + gi);
        Vs4[j * 9 + d4] = *(const float4*)(v + gi);
    }
    __syncthreads();

    // per-lane mask bits: key j = t*32 + lane, t in [0,14)
    unsigned mbits = 0;
    #pragma unroll
    for (int t = 0; t < 14; t++)
        if (mask[b * SEQ + t * 32 + lane]) mbits |= (1u << t);

    const float scale = 0.17677669529663687f;   // 1/sqrt(32)

    // warp handles pairs [warp*28, warp*28+28)
    for (int pp = warp * 28; pp < warp * 28 + 28; pp++) {
        int i0 = pp * 2, i1 = pp * 2 + 1;

        // load both query rows into registers (uniform across lanes)
        float q0[32], q1[32];
        {
            const float4* qp0 = (const float4*)(q + base + (size_t)i0 * D);
            const float4* qp1 = (const float4*)(q + base + (size_t)i1 * D);
            #pragma unroll
            for (int t4 = 0; t4 < 8; t4++) {
                float4 a = qp0[t4];
                q0[t4*4+0]=a.x; q0[t4*4+1]=a.y; q0[t4*4+2]=a.z; q0[t4*4+3]=a.w;
                float4 c = qp1[t4];
                q1[t4*4+0]=c.x; q1[t4*4+1]=c.y; q1[t4*4+2]=c.z; q1[t4*4+3]=c.w;
            }
        }

        // scores for both rows: lane handles keys j = t*32 + lane
        float p0[14], p1[14];
        float mx0 = -1e30f, mx1 = -1e30f;
        #pragma unroll
        for (int t = 0; t < 14; t++) {
            int j = t * 32 + lane;
            const float4* kp = Ks4 + j * 9;
            float s0 = 0.0f, s1 = 0.0f;
            #pragma unroll
            for (int d4 = 0; d4 < 8; d4++) {
                float4 kk = kp[d4];
                s0 = fmaf(q0[d4*4+0], kk.x, s0);
                s0 = fmaf(q0[d4*4+1], kk.y, s0);
                s0 = fmaf(q0[d4*4+2], kk.z, s0);
                s0 = fmaf(q0[d4*4+3], kk.w, s0);
                s1 = fmaf(q1[d4*4+0], kk.x, s1);
                s1 = fmaf(q1[d4*4+1], kk.y, s1);
                s1 = fmaf(q1[d4*4+2], kk.z, s1);
                s1 = fmaf(q1[d4*4+3], kk.w, s1);
            }
            s0 *= scale; s1 *= scale;
            if ((mbits >> t) & 1u) { s0 = -10000.0f; s1 = -10000.0f; }
            p0[t] = s0; p1[t] = s1;
            mx0 = fmaxf(mx0, s0); mx1 = fmaxf(mx1, s1);
        }
        #pragma unroll
        for (int off = 16; off > 0; off >>= 1) {
            mx0 = fmaxf(mx0, __shfl_xor_sync(0xffffffffu, mx0, off));
            mx1 = fmaxf(mx1, __shfl_xor_sync(0xffffffffu, mx1, off));
        }
        float sum0 = 0.0f, sum1 = 0.0f;
        #pragma unroll
        for (int t = 0; t < 14; t++) {
            p0[t] = __expf(p0[t] - mx0); sum0 += p0[t];
            p1[t] = __expf(p1[t] - mx1); sum1 += p1[t];
        }
        #pragma unroll
        for (int off = 16; off > 0; off >>= 1) {
            sum0 += __shfl_xor_sync(0xffffffffu, sum0, off);
            sum1 += __shfl_xor_sync(0xffffffffu, sum1, off);
        }
        float inv0 = 1.0f / sum0, inv1 = 1.0f / sum1;

        // P @ V: lane accumulates its keys' contribution across all 32 dims
        float acc0[32], acc1[32];
        #pragma unroll
        for (int c = 0; c < 32; c++) { acc0[c] = 0.0f; acc1[c] = 0.0f; }
        #pragma unroll
        for (int t = 0; t < 14; t++) {
            int j = t * 32 + lane;
            const float4* vp = Vs4 + j * 9;
            float w0 = p0[t], w1 = p1[t];
            #pragma unroll
            for (int d4 = 0; d4 < 8; d4++) {
                float4 vv = vp[d4];
                acc0[d4*4+0] = fmaf(w0, vv.x, acc0[d4*4+0]);
                acc0[d4*4+1] = fmaf(w0, vv.y, acc0[d4*4+1]);
                acc0[d4*4+2] = fmaf(w0, vv.z, acc0[d4*4+2]);
                acc0[d4*4+3] = fmaf(w0, vv.w, acc0[d4*4+3]);
                acc1[d4*4+0] = fmaf(w1, vv.x, acc1[d4*4+0]);
                acc1[d4*4+1] = fmaf(w1, vv.y, acc1[d4*4+1]);
                acc1[d4*4+2] = fmaf(w1, vv.z, acc1[d4*4+2]);
                acc1[d4*4+3] = fmaf(w1, vv.w, acc1[d4*4+3]);
            }
        }

        // transposed butterfly reduction: after 5 steps lane holds component `lane`
        #pragma unroll
        for (int half = 16; half >= 1; half >>= 1) {
            bool up = (lane & half) != 0;
            #pragma unroll
            for (int c = 0; c < half; c++) {
                float mine0  = up ? acc0[c + half] : acc0[c];
                float send0  = up ? acc0[c]        : acc0[c + half];
                float mine1  = up ? acc1[c + half] : acc1[c];
                float send1  = up ? acc1[c]        : acc1[c + half];
                acc0[c] = mine0 + __shfl_xor_sync(0xffffffffu, send0, half);
                acc1[c] = mine1 + __shfl_xor_sync(0xffffffffu, send1, half);
            }
        }

        o[base + (size_t)i0 * D + lane] = acc0[0] * inv0;
        o[base + (size_t)i1 * D + lane] = acc1[0] * inv1;
    }
}

// ---------------- launch ----------------
extern "C" void kernel_launch(void* const* d_in, const int* in_sizes, int n_in,
                              void* d_out, int out_size) {
    const float* x_in = (const float*)d_in[0];
    const unsigned char* mask = (const unsigned char*)d_in[1];
    const float* pos  = (const float*)d_in[2];
    const float* Wq   = (const float*)d_in[3];
    const float* bq   = (const float*)d_in[4];
    const float* Wk   = (const float*)d_in[5];
    const float* bk   = (const float*)d_in[6];
    const float* Wv   = (const float*)d_in[7];
    const float* bv   = (const float*)d_in[8];
    const float* Wo   = (const float*)d_in[9];
    const float* bo   = (const float*)d_in[10];
    const float* W1   = (const float*)d_in[11];
    const float* bf1  = (const float*)d_in[12];
    const float* W2   = (const float*)d_in[13];
    const float* bf2  = (const float*)d_in[14];
    const float* ln1g = (const float*)d_in[15];
    const float* ln1b = (const float*)d_in[16];
    const float* ln2g = (const float*)d_in[17];
    const float* ln2b = (const float*)d_in[18];
    float* x = (float*)d_out;            // residual stream lives in d_out

    float *nx, *q, *k, *v, *ao, *hb;
    cudaGetSymbolAddress((void**)&nx, g_nx);
    cudaGetSymbolAddress((void**)&q,  g_q);
    cudaGetSymbolAddress((void**)&k,  g_k);
    cudaGetSymbolAddress((void**)&v,  g_v);
    cudaGetSymbolAddress((void**)&ao, g_ao);
    cudaGetSymbolAddress((void**)&hb, g_h);

    int smem_attn = 2 * SEQ * KPAD * sizeof(float);   // 129024 B
    cudaFuncSetAttribute(attn_kernel,
                         cudaFuncAttributeMaxDynamicSharedMemorySize, smem_attn);

    add_pos_kernel<<<(NTOK * D / 4) / 256, 256>>>(x_in, pos, x);

    for (int l = 0; l < NLAYERS; l++) {
        const float* wq = Wq + (size_t)l * D * D;
        const float* wk = Wk + (size_t)l * D * D;
        const float* wv = Wv + (size_t)l * D * D;
        const float* wo = Wo + (size_t)l * D * D;
        const float* w1 = W1 + (size_t)l * D * FFD;
        const float* w2 = W2 + (size_t)l * FFD * D;

        ln_kernel<<<NTOK / 8, 256>>>(x, ln1g + l * D, ln1b + l * D, nx);

        gemm_k<0><<<dim3(2, 112, 3), 256>>>(nx, wq, wk, wv,
                                            bq + l * D, bk + l * D, bv + l * D,
                                            q, k, v, NTOK, D, D);

        attn_kernel<<<BATCH * H, 256, smem_attn>>>(q, k, v, mask, ao);

        gemm_k<2><<<dim3(2, 112, 1), 256>>>(ao, wo, wo, wo,
                                            bo + l * D, bo + l * D, bo + l * D,
                                            x, x, x, NTOK, D, D);

        ln_kernel<<<NTOK / 8, 256>>>(x, ln2g + l * D, ln2b + l * D, nx);

        gemm_k<1><<<dim3(8, 112, 1), 256>>>(nx, w1, w1, w1,
                                            bf1 + l * FFD, bf1 + l * FFD, bf1 + l * FFD,
                                            hb, hb, hb, NTOK, FFD, D);

        gemm_k<2><<<dim3(2, 112, 1), 256>>>(hb, w2, w2, w2,
                                            bf2 + l * D, bf2 + l * D, bf2 + l * D,
                                            x, x, x, NTOK, D, FFD);
    }
}